// round 4
// baseline (speedup 1.0000x reference)
#include <cuda_runtime.h>

#define NQ   6
#define NCL  32
#define NMOD 32
#define PART 64
#define BDIM 64
#define MAXB 2048

typedef unsigned long long u64;

// ---------- packed f32x2 helpers (sm_103a) ----------
__device__ __forceinline__ u64 fma2(u64 a, u64 b, u64 c) {
    u64 d; asm("fma.rn.f32x2 %0, %1, %2, %3;" : "=l"(d) : "l"(a), "l"(b), "l"(c)); return d;
}
__device__ __forceinline__ u64 mul2(u64 a, u64 b) {
    u64 d; asm("mul.rn.f32x2 %0, %1, %2;" : "=l"(d) : "l"(a), "l"(b)); return d;
}
__device__ __forceinline__ u64 add2(u64 a, u64 b) {
    u64 d; asm("add.rn.f32x2 %0, %1, %2;" : "=l"(d) : "l"(a), "l"(b)); return d;
}
__device__ __forceinline__ u64 pk(float lo, float hi) {
    unsigned ulo = __float_as_uint(lo), uhi = __float_as_uint(hi);
    u64 d; asm("mov.b64 %0, {%1, %2};" : "=l"(d) : "r"(ulo), "r"(uhi)); return d;
}
__device__ __forceinline__ void unpk(u64 a, float& lo, float& hi) {
    unsigned ulo, uhi; asm("mov.b64 {%0, %1}, %2;" : "=r"(ulo), "=r"(uhi) : "l"(a));
    lo = __uint_as_float(ulo); hi = __uint_as_float(uhi);
}
__device__ __forceinline__ u64 swp(u64 a) {
    float lo, hi; unpk(a, lo, hi); return pk(hi, lo);
}

// scratch: per-(batch,module) 6 expectation values
__device__ float g_outs[(size_t)MAXB * NMOD * NQ];

// ---------- gates ----------
// Packing: 64-bit reg k holds states s=2k (lo) and s=2k+1 (hi).
// Qubit q (0..4) lives at k-bit (4-q); qubit 5 is the packed lane bit.

template<int MK>
__device__ __forceinline__ void rx_gate(u64 (&R)[32], u64 (&I)[32], u64 c2, u64 s2, u64 ns2) {
#pragma unroll
    for (int k = 0; k < 32; k++) {
        if ((k & MK) == 0) {
            const int k1 = k | MK;
            u64 r0 = R[k], i0 = I[k], r1 = R[k1], i1 = I[k1];
            R[k]  = fma2(c2, r0, mul2(s2,  i1));
            I[k]  = fma2(c2, i0, mul2(ns2, r1));
            R[k1] = fma2(c2, r1, mul2(s2,  i0));
            I[k1] = fma2(c2, i1, mul2(ns2, r0));
        }
    }
}

// RX on qubit 5: pair is within the packed lanes
__device__ __forceinline__ void rx_gate5(u64 (&R)[32], u64 (&I)[32], u64 c2, u64 s2, u64 ns2) {
#pragma unroll
    for (int k = 0; k < 32; k++) {
        u64 rs = swp(R[k]);
        u64 is = swp(I[k]);
        R[k] = fma2(c2, R[k], mul2(s2,  is));
        I[k] = fma2(c2, I[k], mul2(ns2, rs));
    }
}

template<int MC, int MT>
__device__ __forceinline__ void cnot_kk(u64 (&R)[32], u64 (&I)[32]) {
#pragma unroll
    for (int k = 0; k < 32; k++) {
        if ((k & MC) && !(k & MT)) {
            const int k1 = k | MT;
            u64 t = R[k]; R[k] = R[k1]; R[k1] = t;
            t = I[k]; I[k] = I[k1]; I[k1] = t;
        }
    }
}

// CNOT(ctrl=q4 -> tgt=q5): for k odd, swap packed lanes
__device__ __forceinline__ void cnot_45(u64 (&R)[32], u64 (&I)[32]) {
#pragma unroll
    for (int k = 1; k < 32; k += 2) {
        R[k] = swp(R[k]);
        I[k] = swp(I[k]);
    }
}

// CNOT(ctrl=q5 -> tgt=q0): exchange hi lanes between k and k+16
__device__ __forceinline__ void cnot_50(u64 (&R)[32], u64 (&I)[32]) {
#pragma unroll
    for (int k = 0; k < 16; k++) {
        float alo, ahi, blo, bhi;
        unpk(R[k], alo, ahi); unpk(R[k | 16], blo, bhi);
        R[k] = pk(alo, bhi); R[k | 16] = pk(blo, ahi);
        unpk(I[k], alo, ahi); unpk(I[k | 16], blo, bhi);
        I[k] = pk(alo, bhi); I[k | 16] = pk(blo, ahi);
    }
}

// ---------- simulation kernel: one thread = one (batch, module) circuit ----------
__global__ __launch_bounds__(BDIM)
void sim_kernel(const float* __restrict__ feat,
                const float* __restrict__ Wp,
                const float* __restrict__ bp,
                const float* __restrict__ qw,
                int B)
{
    __shared__ u64 tC[NCL * NQ], tS[NCL * NQ], tNS[NCL * NQ];
    __shared__ float sWp[NQ * PART];
    __shared__ float sbp[NQ];

    const int tid = threadIdx.x;
    const int p = blockIdx.y;  // module

    // per-module gate table (cos/sin of layer weights), packed
    for (int i = tid; i < NCL * NQ; i += BDIM) {
        float w = qw[p * (NCL * NQ) + i];
        float s, c; sincosf(w * 0.5f, &s, &c);
        tC[i]  = pk(c, c);
        tS[i]  = pk(s, s);
        tNS[i] = pk(-s, -s);
    }
    for (int i = tid; i < NQ * PART; i += BDIM) sWp[i] = Wp[i];
    if (tid < NQ) sbp[tid] = bp[tid];
    __syncthreads();

    const int b = blockIdx.x * BDIM + tid;
    if (b >= B || b >= MAXB) return;

    // angles[q] = dot(features[b, p*64 : p*64+64], Wp[q]) + bp[q]
    float ang[NQ];
#pragma unroll
    for (int q = 0; q < NQ; q++) ang[q] = sbp[q];
    const float4* f4 = reinterpret_cast<const float4*>(feat + (size_t)b * 2048 + p * PART);
#pragma unroll
    for (int d = 0; d < 16; d++) {
        float4 v = f4[d];
#pragma unroll
        for (int q = 0; q < NQ; q++) {
            ang[q] += v.x * sWp[q * PART + 4 * d + 0] + v.y * sWp[q * PART + 4 * d + 1]
                    + v.z * sWp[q * PART + 4 * d + 2] + v.w * sWp[q * PART + 4 * d + 3];
        }
    }
    float cs[NQ], sn[NQ];
#pragma unroll
    for (int q = 0; q < NQ; q++) sincosf(ang[q] * 0.5f, &sn[q], &cs[q]);

    // initial product state (real): v32[k] = prod over qubits 0..4
    float v2[2], v4[4], v8[8], v16[16], v32[32];
    v2[0] = cs[0]; v2[1] = sn[0];
#pragma unroll
    for (int i = 0; i < 2; i++)  { v4[2*i]  = v2[i]*cs[1];  v4[2*i+1]  = v2[i]*sn[1]; }
#pragma unroll
    for (int i = 0; i < 4; i++)  { v8[2*i]  = v4[i]*cs[2];  v8[2*i+1]  = v4[i]*sn[2]; }
#pragma unroll
    for (int i = 0; i < 8; i++)  { v16[2*i] = v8[i]*cs[3];  v16[2*i+1] = v8[i]*sn[3]; }
#pragma unroll
    for (int i = 0; i < 16; i++) { v32[2*i] = v16[i]*cs[4]; v32[2*i+1] = v16[i]*sn[4]; }

    u64 R[32], I[32];
#pragma unroll
    for (int k = 0; k < 32; k++) {
        R[k] = pk(v32[k] * cs[5], v32[k] * sn[5]);  // lane = qubit-5 bit
        I[k] = 0ULL;
    }

    // 32 layers: 6 RX then CNOT ring
    for (int l = 0; l < NCL; l++) {
        const int o = l * NQ;
        rx_gate<16>(R, I, tC[o + 0], tS[o + 0], tNS[o + 0]);  // qubit 0
        rx_gate<8>(R, I, tC[o + 1], tS[o + 1], tNS[o + 1]);   // qubit 1
        rx_gate<4>(R, I, tC[o + 2], tS[o + 2], tNS[o + 2]);   // qubit 2
        rx_gate<2>(R, I, tC[o + 3], tS[o + 3], tNS[o + 3]);   // qubit 3
        rx_gate<1>(R, I, tC[o + 4], tS[o + 4], tNS[o + 4]);   // qubit 4
        rx_gate5(R, I, tC[o + 5], tS[o + 5], tNS[o + 5]);     // qubit 5
        cnot_kk<16, 8>(R, I);  // (0,1)
        cnot_kk<8, 4>(R, I);   // (1,2)
        cnot_kk<4, 2>(R, I);   // (2,3)
        cnot_kk<2, 1>(R, I);   // (3,4)
        cnot_45(R, I);         // (4,5)
        cnot_50(R, I);         // (5,0)
    }

    // probabilities + Z expectations
    u64 pr[32];
#pragma unroll
    for (int k = 0; k < 32; k++) pr[k] = fma2(R[k], R[k], mul2(I[k], I[k]));

    u64 S = pr[0];
#pragma unroll
    for (int k = 1; k < 32; k++) S = add2(S, pr[k]);
    float Sl, Sh; unpk(S, Sl, Sh);
    const float tot = Sl + Sh;

    float z[NQ];
    z[5] = Sl - Sh;
#pragma unroll
    for (int j = 0; j < 5; j++) {
        const int m = 1 << (4 - j);
        u64 T = pr[m];
#pragma unroll
        for (int k = 0; k < 32; k++) {
            if ((k & m) && k != m) T = add2(T, pr[k]);
        }
        float Tl, Th; unpk(T, Tl, Th);
        z[j] = tot - 2.0f * (Tl + Th);
    }

    float* o = g_outs + (size_t)b * (NMOD * NQ) + p * NQ;
#pragma unroll
    for (int j = 0; j < NQ; j++) o[j] = z[j];
}

// ---------- final projection: out[b,c] = sum_k outs[b,k]*Wf[c,k] + bf[c] ----------
__global__ void final_kernel(const float* __restrict__ Wf,
                             const float* __restrict__ bf,
                             float* __restrict__ out,
                             int B, int C)
{
    __shared__ float sh[32 * 192];
    const int tid = threadIdx.x;
    const int b0 = blockIdx.x * 32;

    for (int i = tid; i < 32 * 192; i += blockDim.x) {
        const int bb = i / 192;
        sh[i] = (b0 + bb < B) ? g_outs[(size_t)(b0 + bb) * 192 + (i % 192)] : 0.0f;
    }
    __syncthreads();

    const int c = tid;
    if (c < C) {
        float acc[32];
#pragma unroll
        for (int i = 0; i < 32; i++) acc[i] = 0.0f;
        const float* w = Wf + (size_t)c * 192;
        for (int k = 0; k < 192; k++) {
            const float wv = __ldg(w + k);
#pragma unroll
            for (int i = 0; i < 32; i++) acc[i] += sh[i * 192 + k] * wv;
        }
        const float bv = bf[c];
#pragma unroll
        for (int i = 0; i < 32; i++) {
            if (b0 + i < B) out[(size_t)(b0 + i) * C + c] = acc[i] + bv;
        }
    }
}

extern "C" void kernel_launch(void* const* d_in, const int* in_sizes, int n_in,
                              void* d_out, int out_size)
{
    const float* feat = (const float*)d_in[0];
    const float* Wp   = (const float*)d_in[1];
    const float* bp   = (const float*)d_in[2];
    const float* qw   = (const float*)d_in[3];
    const float* Wf   = (const float*)d_in[4];
    const float* bf   = (const float*)d_in[5];
    float* out = (float*)d_out;

    const int B = in_sizes[0] / 2048;          // 2048
    const int C = in_sizes[4] / (NMOD * NQ);   // 150

    dim3 grid((B + BDIM - 1) / BDIM, NMOD);
    sim_kernel<<<grid, BDIM>>>(feat, Wp, bp, qw, B);

    int threads = ((C + 31) / 32) * 32;        // 160
    final_kernel<<<(B + 31) / 32, threads>>>(Wf, bf, out, B, C);
}

// round 5
// speedup vs baseline: 1.9910x; 1.9910x over previous
#include <cuda_runtime.h>

#define NQ   6
#define NCL  32
#define NMOD 32
#define PART 64
#define MAXB 2048

typedef unsigned long long u64;

// ---------- packed f32x2 helpers (sm_103a) ----------
__device__ __forceinline__ u64 fma2(u64 a, u64 b, u64 c) {
    u64 d; asm("fma.rn.f32x2 %0, %1, %2, %3;" : "=l"(d) : "l"(a), "l"(b), "l"(c)); return d;
}
__device__ __forceinline__ u64 mul2(u64 a, u64 b) {
    u64 d; asm("mul.rn.f32x2 %0, %1, %2;" : "=l"(d) : "l"(a), "l"(b)); return d;
}
__device__ __forceinline__ u64 pk(float lo, float hi) {
    unsigned ulo = __float_as_uint(lo), uhi = __float_as_uint(hi);
    u64 d; asm("mov.b64 %0, {%1, %2};" : "=l"(d) : "r"(ulo), "r"(uhi)); return d;
}
__device__ __forceinline__ void unpk(u64 a, float& lo, float& hi) {
    unsigned ulo, uhi; asm("mov.b64 {%0, %1}, %2;" : "=r"(ulo), "=r"(uhi) : "l"(a));
    lo = __uint_as_float(ulo); hi = __uint_as_float(uhi);
}
__device__ __forceinline__ u64 swp(u64 a) {
    float lo, hi; unpk(a, lo, hi); return pk(hi, lo);
}

// scratch
__device__ u64   g_U[(size_t)NMOD * 64 * 64];       // [p][j][s] packed (re,im) — 1MB
__device__ float g_outs[(size_t)MAXB * NMOD * NQ];

// ---------- gates (register statevector; qubit q<=4 at k-bit (4-q), qubit5 = lane) ----------
template<int MK>
__device__ __forceinline__ void rx_gate(u64 (&R)[32], u64 (&I)[32], u64 c2, u64 s2, u64 ns2) {
#pragma unroll
    for (int k = 0; k < 32; k++) {
        if ((k & MK) == 0) {
            const int k1 = k | MK;
            u64 r0 = R[k], i0 = I[k], r1 = R[k1], i1 = I[k1];
            R[k]  = fma2(c2, r0, mul2(s2,  i1));
            I[k]  = fma2(c2, i0, mul2(ns2, r1));
            R[k1] = fma2(c2, r1, mul2(s2,  i0));
            I[k1] = fma2(c2, i1, mul2(ns2, r0));
        }
    }
}
__device__ __forceinline__ void rx_gate5(u64 (&R)[32], u64 (&I)[32], u64 c2, u64 s2, u64 ns2) {
#pragma unroll
    for (int k = 0; k < 32; k++) {
        u64 rs = swp(R[k]);
        u64 is = swp(I[k]);
        R[k] = fma2(c2, R[k], mul2(s2,  is));
        I[k] = fma2(c2, I[k], mul2(ns2, rs));
    }
}
template<int MC, int MT>
__device__ __forceinline__ void cnot_kk(u64 (&R)[32], u64 (&I)[32]) {
#pragma unroll
    for (int k = 0; k < 32; k++) {
        if ((k & MC) && !(k & MT)) {
            const int k1 = k | MT;
            u64 t = R[k]; R[k] = R[k1]; R[k1] = t;
            t = I[k]; I[k] = I[k1]; I[k1] = t;
        }
    }
}
__device__ __forceinline__ void cnot_45(u64 (&R)[32], u64 (&I)[32]) {
#pragma unroll
    for (int k = 1; k < 32; k += 2) { R[k] = swp(R[k]); I[k] = swp(I[k]); }
}
__device__ __forceinline__ void cnot_50(u64 (&R)[32], u64 (&I)[32]) {
#pragma unroll
    for (int k = 0; k < 16; k++) {
        float alo, ahi, blo, bhi;
        unpk(R[k], alo, ahi); unpk(R[k | 16], blo, bhi);
        R[k] = pk(alo, bhi); R[k | 16] = pk(blo, ahi);
        unpk(I[k], alo, ahi); unpk(I[k | 16], blo, bhi);
        I[k] = pk(alo, bhi); I[k | 16] = pk(blo, ahi);
    }
}

// ---------- kernel 1: build per-module 64x64 unitary (thread = one basis column) ----------
__global__ __launch_bounds__(32)
void unitary_kernel(const float* __restrict__ qw)
{
    __shared__ u64 tC[NCL * NQ], tS[NCL * NQ], tNS[NCL * NQ];
    const int tid = threadIdx.x;
    const int p = blockIdx.x >> 1;
    const int j = ((blockIdx.x & 1) << 5) + tid;

    for (int i = tid; i < NCL * NQ; i += 32) {
        float w = qw[p * (NCL * NQ) + i];
        float s, c; sincosf(w * 0.5f, &s, &c);
        tC[i] = pk(c, c); tS[i] = pk(s, s); tNS[i] = pk(-s, -s);
    }
    __syncthreads();

    // init state = e_j  (s = 2k + lane; j's pair index = j>>1, lane = j&1)
    u64 R[32], I[32];
    const int kj = j >> 1;
    const int lj = j & 1;
#pragma unroll
    for (int k = 0; k < 32; k++) {
        R[k] = (k == kj) ? (lj ? pk(0.0f, 1.0f) : pk(1.0f, 0.0f)) : 0ULL;
        I[k] = 0ULL;
    }

    for (int l = 0; l < NCL; l++) {
        const int o = l * NQ;
        rx_gate<16>(R, I, tC[o + 0], tS[o + 0], tNS[o + 0]);
        rx_gate<8>(R, I, tC[o + 1], tS[o + 1], tNS[o + 1]);
        rx_gate<4>(R, I, tC[o + 2], tS[o + 2], tNS[o + 2]);
        rx_gate<2>(R, I, tC[o + 3], tS[o + 3], tNS[o + 3]);
        rx_gate<1>(R, I, tC[o + 4], tS[o + 4], tNS[o + 4]);
        rx_gate5(R, I, tC[o + 5], tS[o + 5], tNS[o + 5]);
        cnot_kk<16, 8>(R, I);
        cnot_kk<8, 4>(R, I);
        cnot_kk<4, 2>(R, I);
        cnot_kk<2, 1>(R, I);
        cnot_45(R, I);
        cnot_50(R, I);
    }

    // store column j: g_U[p][j][s] = (re_s, im_s) packed
    u64* dst = g_U + ((size_t)p * 64 + j) * 64;
#pragma unroll
    for (int k = 0; k < 32; k++) {
        float r0, r1, i0, i1;
        unpk(R[k], r0, r1); unpk(I[k], i0, i1);
        dst[2 * k]     = pk(r0, i0);
        dst[2 * k + 1] = pk(r1, i1);
    }
}

// ---------- kernel 2: per-(batch,module) matvec + Z expectations ----------
// block = (64 batches, module p); 128 threads: tid&63 = batch, tid>>6 = output half
__global__ __launch_bounds__(128)
void matvec_kernel(const float* __restrict__ feat,
                   const float* __restrict__ Wp,
                   const float* __restrict__ bp,
                   int B)
{
    __shared__ u64   sU[64 * 64];      // 32KB, [j*64 + s]
    __shared__ float sv32[64 * 33];    // per-batch product amps over qubits0..4
    __shared__ float s5[64 * 3];       // per-batch (cos5, sin5)
    __shared__ float sWp[NQ * PART];
    __shared__ float sbp[NQ];
    __shared__ float zred[128 * 9];    // per-thread partial (T, M0..M5)

    const int tid  = threadIdx.x;
    const int p    = blockIdx.y;
    const int bl   = tid & 63;
    const int half = tid >> 6;
    const int b    = blockIdx.x * 64 + bl;

    // stage U_p
    const u64* gu = g_U + (size_t)p * 64 * 64;
#pragma unroll
    for (int i = 0; i < 32; i++) sU[tid + i * 128] = gu[tid + i * 128];

    for (int i = tid; i < NQ * PART; i += 128) sWp[i] = Wp[i];
    if (tid < NQ) sbp[tid] = bp[tid];
    __syncthreads();

    if (half == 0 && b < B) {
        // angles[q] = dot(features[b, p*64:+64], Wp[q]) + bp[q]
        float ang[NQ];
#pragma unroll
        for (int q = 0; q < NQ; q++) ang[q] = sbp[q];
        const float4* f4 = reinterpret_cast<const float4*>(feat + (size_t)b * 2048 + p * PART);
#pragma unroll
        for (int d = 0; d < 16; d++) {
            float4 v = f4[d];
#pragma unroll
            for (int q = 0; q < NQ; q++) {
                ang[q] += v.x * sWp[q * PART + 4 * d + 0] + v.y * sWp[q * PART + 4 * d + 1]
                        + v.z * sWp[q * PART + 4 * d + 2] + v.w * sWp[q * PART + 4 * d + 3];
            }
        }
        float cs[NQ], sn[NQ];
#pragma unroll
        for (int q = 0; q < NQ; q++) sincosf(ang[q] * 0.5f, &sn[q], &cs[q]);

        float v2[2], v4[4], v8[8], v16[16];
        v2[0] = cs[0]; v2[1] = sn[0];
#pragma unroll
        for (int i = 0; i < 2; i++)  { v4[2*i]  = v2[i]*cs[1];  v4[2*i+1]  = v2[i]*sn[1]; }
#pragma unroll
        for (int i = 0; i < 4; i++)  { v8[2*i]  = v4[i]*cs[2];  v8[2*i+1]  = v4[i]*sn[2]; }
#pragma unroll
        for (int i = 0; i < 8; i++)  { v16[2*i] = v8[i]*cs[3];  v16[2*i+1] = v8[i]*sn[3]; }
#pragma unroll
        for (int i = 0; i < 16; i++) {
            sv32[bl * 33 + 2*i]     = v16[i]*cs[4];
            sv32[bl * 33 + 2*i + 1] = v16[i]*sn[4];
        }
        s5[bl * 3 + 0] = cs[5];
        s5[bl * 3 + 1] = sn[5];
    }
    __syncthreads();

    // out[s] = sum_j U[s][j] * v[j]   (v real, U complex packed)
    u64 out2[32];
#pragma unroll
    for (int t = 0; t < 32; t++) out2[t] = 0ULL;

    const float c5 = s5[bl * 3 + 0];
    const float n5 = s5[bl * 3 + 1];
    const float* vb = sv32 + bl * 33;

    for (int jo = 0; jo < 64; jo += 8) {
#pragma unroll
        for (int ju = 0; ju < 8; ju++) {
            const float vbase = vb[(jo + ju) >> 1];
            const float vj = vbase * ((ju & 1) ? n5 : c5);
            const u64 vv = pk(vj, vj);
            const ulonglong2* col =
                reinterpret_cast<const ulonglong2*>(sU + (jo + ju) * 64 + half * 32);
#pragma unroll
            for (int t = 0; t < 16; t++) {
                ulonglong2 u = col[t];
                out2[2 * t]     = fma2(vv, u.x, out2[2 * t]);
                out2[2 * t + 1] = fma2(vv, u.y, out2[2 * t + 1]);
            }
        }
    }

    // partial Z sums over this thread's 32 basis states
    float T = 0.0f, M[NQ];
#pragma unroll
    for (int q = 0; q < NQ; q++) M[q] = 0.0f;
#pragma unroll
    for (int t = 0; t < 32; t++) {
        const int s = half * 32 + t;
        float re, im; unpk(out2[t], re, im);
        const float pr = re * re + im * im;
        T += pr;
#pragma unroll
        for (int q = 0; q < NQ; q++)
            if ((s >> (5 - q)) & 1) M[q] += pr;
    }
    float* zr = zred + tid * 9;
    zr[0] = T;
#pragma unroll
    for (int q = 0; q < NQ; q++) zr[1 + q] = M[q];
    __syncthreads();

    if (half == 0 && b < B) {
        const float* a0 = zred + tid * 9;
        const float* a1 = zred + (tid + 64) * 9;
        const float Tt = a0[0] + a1[0];
        float* o = g_outs + (size_t)b * (NMOD * NQ) + p * NQ;
#pragma unroll
        for (int q = 0; q < NQ; q++)
            o[q] = Tt - 2.0f * (a0[1 + q] + a1[1 + q]);
    }
}

// ---------- kernel 3: out[b,c] = outs[b,:] . Wf[c,:] + bf[c] ----------
__global__ __launch_bounds__(160)
void final_kernel(const float* __restrict__ Wf,
                  const float* __restrict__ bf,
                  float* __restrict__ out,
                  int B, int C)
{
    __shared__ float sh[8 * 192];
    const int tid = threadIdx.x;
    const int b0  = blockIdx.x * 8;

    const float4* src = reinterpret_cast<const float4*>(g_outs + (size_t)b0 * 192);
    float4* dsh = reinterpret_cast<float4*>(sh);
    for (int i = tid; i < 8 * 192 / 4; i += blockDim.x) dsh[i] = src[i];
    __syncthreads();

    const int c = tid;
    if (c < C) {
        float acc[8];
#pragma unroll
        for (int i = 0; i < 8; i++) acc[i] = 0.0f;
        const float4* w = reinterpret_cast<const float4*>(Wf + (size_t)c * 192);
#pragma unroll 4
        for (int k4 = 0; k4 < 48; k4++) {
            const float4 wv = __ldg(w + k4);
#pragma unroll
            for (int i = 0; i < 8; i++) {
                acc[i] += sh[i * 192 + 4 * k4 + 0] * wv.x
                        + sh[i * 192 + 4 * k4 + 1] * wv.y
                        + sh[i * 192 + 4 * k4 + 2] * wv.z
                        + sh[i * 192 + 4 * k4 + 3] * wv.w;
            }
        }
        const float bv = bf[c];
#pragma unroll
        for (int i = 0; i < 8; i++) {
            if (b0 + i < B) out[(size_t)(b0 + i) * C + c] = acc[i] + bv;
        }
    }
}

extern "C" void kernel_launch(void* const* d_in, const int* in_sizes, int n_in,
                              void* d_out, int out_size)
{
    const float* feat = (const float*)d_in[0];
    const float* Wp   = (const float*)d_in[1];
    const float* bp   = (const float*)d_in[2];
    const float* qw   = (const float*)d_in[3];
    const float* Wf   = (const float*)d_in[4];
    const float* bf   = (const float*)d_in[5];
    float* out = (float*)d_out;

    const int B = in_sizes[0] / 2048;          // 2048
    const int C = in_sizes[4] / (NMOD * NQ);   // 150

    // 1. per-module unitaries (32 modules x 64 columns, 1 column per thread)
    unitary_kernel<<<NMOD * 2, 32>>>(qw);

    // 2. batched matvec + Z expectations
    dim3 grid((B + 63) / 64, NMOD);
    matvec_kernel<<<grid, 128>>>(feat, Wp, bp, B);

    // 3. final projection
    final_kernel<<<(B + 7) / 8, 160>>>(Wf, bf, out, B, C);
}